// round 12
// baseline (speedup 1.0000x reference)
#include <cuda_runtime.h>
#include <cstdint>
#include <math_constants.h>

#define TOKENS   32768
#define DIM      2048
#define NE       64
#define TOPK     6

#define BM       128              // tokens per CTA
#define BKT      32               // K per chunk
#define NCHUNK   (DIM / BKT)      // 64
#define THREADS  256              // 8 warps: 4 across M (32 rows), 2 across N (32 cols)

#define KB2      40               // bf16 row stride (elements): 32 + 8 pad -> conflict-free frags
#define ROWB     (KB2 * 2)        // 80 bytes per row

#define OFF_AH   0
#define OFF_AM   (BM * ROWB)                       // 10240
#define OFF_WH   (2 * BM * ROWB)                   // 20480
#define OFF_WM   (2 * BM * ROWB + NE * ROWB)       // 25600
#define STAGE_B  (2 * BM * ROWB + 2 * NE * ROWB)   // 30720
#define BIAS_OFF (2 * STAGE_B)
#define SMEM_BYTES (BIAS_OFF + 256)

#define LSTR     66               // epilogue logits row stride (floats)
#define FLAG_GAP 2e-5f            // >=10 sigma above 3-term bf16 score noise (~2e-6)

// ---- flat flagged-token list ----
__device__ int g_nflag;
__device__ int g_flags[TOKENS];

// pack two fp32 -> bf16x2, round-to-nearest
__device__ __forceinline__ uint32_t pack_bf16(float hi, float lo) {
    uint32_t d;
    asm("cvt.rn.bf16x2.f32 %0, %1, %2;" : "=r"(d) : "f"(hi), "f"(lo));
    return d;
}
__device__ __forceinline__ float bf_lo(uint32_t p) { return __uint_as_float(p << 16); }
__device__ __forceinline__ float bf_hi(uint32_t p) { return __uint_as_float(p & 0xFFFF0000u); }

struct Duo { uint2 h, m; };
// 2-way bf16 split of 4 consecutive values: v ~= h + m (residual ~2^-17 rel)
__device__ __forceinline__ Duo split4(float4 v) {
    Duo t;
    t.h.x = pack_bf16(v.y, v.x);
    t.h.y = pack_bf16(v.w, v.z);
    float r0 = v.x - bf_lo(t.h.x), r1 = v.y - bf_hi(t.h.x);
    float r2 = v.z - bf_lo(t.h.y), r3 = v.w - bf_hi(t.h.y);
    t.m.x = pack_bf16(r1, r0);
    t.m.y = pack_bf16(r3, r2);
    return t;
}

// m16n8k16 bf16 mma, f32 accumulate in-place
__device__ __forceinline__ void mma16(float* c, const uint32_t* a, uint32_t b0, uint32_t b1) {
    asm volatile(
        "mma.sync.aligned.m16n8k16.row.col.f32.bf16.bf16.f32 "
        "{%0,%1,%2,%3}, {%4,%5,%6,%7}, {%8,%9}, {%0,%1,%2,%3};"
        : "+f"(c[0]), "+f"(c[1]), "+f"(c[2]), "+f"(c[3])
        : "r"(a[0]), "r"(a[1]), "r"(a[2]), "r"(a[3]), "r"(b0), "r"(b1));
}

// ============================ PASS 1: bf16 3-term MMA GEMM + gate ============================
__global__ __launch_bounds__(THREADS, 2)
void gate_kernel(const float* __restrict__ x,
                 const float* __restrict__ w,
                 const float* __restrict__ bias,
                 float* __restrict__ out)
{
    extern __shared__ __align__(16) unsigned char smem[];
    float* sBias = reinterpret_cast<float*>(smem + BIAS_OFF);
    float* sLog  = reinterpret_cast<float*>(smem);   // epilogue overlay

    const int tid  = threadIdx.x;
    const int lane = tid & 31;
    const int wid  = tid >> 5;
    const int gid  = lane >> 2;
    const int tg   = lane & 3;
    const int m0   = (wid & 3) * 32;
    const int n0   = (wid >> 2) * 32;
    const int block_m = blockIdx.x * BM;

    if (tid < NE) sBias[tid] = bias[tid];

    const float* xg = x + (size_t)block_m * DIM;

    float acc[2][4][4];
    #pragma unroll
    for (int mt = 0; mt < 2; mt++)
        #pragma unroll
        for (int nt = 0; nt < 4; nt++)
            #pragma unroll
            for (int r = 0; r < 4; r++) acc[mt][nt][r] = 0.f;

    float4 xr[4], wr[2];
    int xtok[4], xcq[4], wexp[2], wcq[2];
    #pragma unroll
    for (int i = 0; i < 4; i++) {
        int li = i * THREADS + tid; xtok[i] = li >> 3; xcq[i] = li & 7;
    }
    #pragma unroll
    for (int i = 0; i < 2; i++) {
        int li = i * THREADS + tid; wexp[i] = li >> 3; wcq[i] = li & 7;
    }

    auto ldg_chunk = [&](int c) {
        int k0 = c * BKT;
        #pragma unroll
        for (int i = 0; i < 4; i++)
            xr[i] = *reinterpret_cast<const float4*>(xg + (size_t)xtok[i] * DIM + k0 + xcq[i] * 4);
        #pragma unroll
        for (int i = 0; i < 2; i++)
            wr[i] = *reinterpret_cast<const float4*>(w + (size_t)wexp[i] * DIM + k0 + wcq[i] * 4);
    };
    auto sts_chunk = [&](int s) {
        unsigned char* st = smem + s * STAGE_B;
        #pragma unroll
        for (int i = 0; i < 4; i++) {
            Duo t = split4(xr[i]);
            int off = xtok[i] * ROWB + xcq[i] * 8;
            *reinterpret_cast<uint2*>(st + OFF_AH + off) = t.h;
            *reinterpret_cast<uint2*>(st + OFF_AM + off) = t.m;
        }
        #pragma unroll
        for (int i = 0; i < 2; i++) {
            Duo t = split4(wr[i]);
            int off = wexp[i] * ROWB + wcq[i] * 8;
            *reinterpret_cast<uint2*>(st + OFF_WH + off) = t.h;
            *reinterpret_cast<uint2*>(st + OFF_WM + off) = t.m;
        }
    };

    ldg_chunk(0);
    sts_chunk(0);
    __syncthreads();
    ldg_chunk(1);

    for (int c = 0; c < NCHUNK; c++) {
        const int s = c & 1;
        if (c + 1 < NCHUNK) {
            sts_chunk(s ^ 1);
            if (c + 2 < NCHUNK) ldg_chunk(c + 2);
        }

        const unsigned char* st = smem + s * STAGE_B;
        const uint32_t* Ah = reinterpret_cast<const uint32_t*>(st + OFF_AH);
        const uint32_t* Am = reinterpret_cast<const uint32_t*>(st + OFF_AM);
        const uint32_t* Wh = reinterpret_cast<const uint32_t*>(st + OFF_WH);
        const uint32_t* Wm = reinterpret_cast<const uint32_t*>(st + OFF_WM);

        #pragma unroll
        for (int q = 0; q < BKT / 16; q++) {
            const int kw = q * 8 + tg;

            uint32_t ah[2][4], am[2][4];
            #pragma unroll
            for (int mt = 0; mt < 2; mt++) {
                int r0 = (m0 + mt * 16 + gid) * (ROWB / 4);
                int r1 = r0 + 8 * (ROWB / 4);
                ah[mt][0] = Ah[r0 + kw];     ah[mt][1] = Ah[r1 + kw];
                ah[mt][2] = Ah[r0 + kw + 4]; ah[mt][3] = Ah[r1 + kw + 4];
                am[mt][0] = Am[r0 + kw];     am[mt][1] = Am[r1 + kw];
                am[mt][2] = Am[r0 + kw + 4]; am[mt][3] = Am[r1 + kw + 4];
            }

            #pragma unroll
            for (int nt = 0; nt < 4; nt++) {
                int rn = (n0 + nt * 8 + gid) * (ROWB / 4);
                uint32_t bh0 = Wh[rn + kw], bh1 = Wh[rn + kw + 4];
                uint32_t bm0 = Wm[rn + kw], bm1 = Wm[rn + kw + 4];
                #pragma unroll
                for (int mt = 0; mt < 2; mt++) {
                    float* cc = acc[mt][nt];
                    mma16(cc, ah[mt], bh0, bh1);   // hi*hi
                    mma16(cc, ah[mt], bm0, bm1);   // hi*mid
                    mma16(cc, am[mt], bh0, bh1);   // mid*hi
                }
            }
        }
        __syncthreads();
    }

    // ---- dump logits ----
    #pragma unroll
    for (int mt = 0; mt < 2; mt++)
        #pragma unroll
        for (int nt = 0; nt < 4; nt++) {
            int row = m0 + mt * 16 + gid;
            int col = n0 + nt * 8 + tg * 2;
            *reinterpret_cast<float2*>(&sLog[row * LSTR + col]) =
                make_float2(acc[mt][nt][0], acc[mt][nt][1]);
            *reinterpret_cast<float2*>(&sLog[(row + 8) * LSTR + col]) =
                make_float2(acc[mt][nt][2], acc[mt][nt][3]);
        }
    __syncthreads();

    // ---- epilogue: softmax, top-6, ambiguity flag ----
    if (tid < BM) {
        float* row = sLog + tid * LSTR;

        float m = row[0];
        #pragma unroll
        for (int e = 1; e < NE; e++) m = fmaxf(m, row[e]);
        float ssum = 0.f;
        #pragma unroll
        for (int e = 0; e < NE; e++) { float ex = __expf(row[e] - m); row[e] = ex; ssum += ex; }
        float inv = 1.0f / ssum;
        #pragma unroll
        for (int e = 0; e < NE; e++) row[e] *= inv;

        const int t = block_m + tid;
        float* outw = out + (size_t)t * TOPK;
        float* outi = out + (size_t)TOKENS * TOPK + (size_t)t * TOPK;

        float prev = 0.f, minGap = CUDART_INF_F;
        #pragma unroll
        for (int k = 0; k < TOPK + 1; k++) {
            float best = -CUDART_INF_F; int bi = 0;
            #pragma unroll
            for (int e = 0; e < NE; e++) {
                float b = row[e] + sBias[e];
                if (b > best) { best = b; bi = e; }
            }
            if (k > 0) minGap = fminf(minGap, prev - best);
            prev = best;
            if (k < TOPK) {
                outw[k] = row[bi];
                outi[k] = (float)bi;
                row[bi] = -CUDART_INF_F;
            }
        }
        if (minGap < FLAG_GAP) {
            int idx = atomicAdd(&g_nflag, 1);
            g_flags[idx] = t;
        }
    }
}

// ============ PASS 2: fp32 recompute for flagged tokens, 1 block/token ============
// 256 threads: expert = tid&63, k-quarter = tid>>6 (4 x 512-long k-ascending dots,
// combined in ascending-quarter order).
__global__ __launch_bounds__(256)
void fix_kernel(const float* __restrict__ x,
                const float* __restrict__ w,
                const float* __restrict__ bias,
                float* __restrict__ out)
{
    __shared__ float part[4][NE];
    __shared__ float row[NE];

    const int n = g_nflag;
    const int e  = threadIdx.x & 63;
    const int qt = threadIdx.x >> 6;       // 0..3

    for (int i = blockIdx.x; i < n; i += gridDim.x) {
        const int tok = g_flags[i];
        const float* xt = x + (size_t)tok * DIM + qt * (DIM / 4);
        const float* wt = w + (size_t)e * DIM + qt * (DIM / 4);

        float a = 0.f;
        #pragma unroll 8
        for (int k = 0; k < DIM / 4; k += 4) {
            float4 xv = *reinterpret_cast<const float4*>(xt + k);
            float4 wv = *reinterpret_cast<const float4*>(wt + k);
            a = fmaf(xv.x, wv.x, a); a = fmaf(xv.y, wv.y, a);
            a = fmaf(xv.z, wv.z, a); a = fmaf(xv.w, wv.w, a);
        }
        part[qt][e] = a;
        __syncthreads();

        if (threadIdx.x < NE) {
            row[threadIdx.x] = ((part[0][threadIdx.x] + part[1][threadIdx.x])
                              + part[2][threadIdx.x]) + part[3][threadIdx.x];
        }
        __syncthreads();

        if (threadIdx.x == 0) {
            float m = row[0];
            #pragma unroll
            for (int q = 1; q < NE; q++) m = fmaxf(m, row[q]);
            float ssum = 0.f;
            #pragma unroll
            for (int q = 0; q < NE; q++) { float ex = __expf(row[q] - m); row[q] = ex; ssum += ex; }
            float inv = 1.0f / ssum;
            #pragma unroll
            for (int q = 0; q < NE; q++) row[q] *= inv;

            float* outw = out + (size_t)tok * TOPK;
            float* outi = out + (size_t)TOKENS * TOPK + (size_t)tok * TOPK;
            #pragma unroll
            for (int k = 0; k < TOPK; k++) {
                float best = -CUDART_INF_F; int bi = 0;
                #pragma unroll
                for (int q = 0; q < NE; q++) {
                    float b = row[q] + __ldg(&bias[q]);
                    if (b > best) { best = b; bi = q; }
                }
                outw[k] = row[bi];
                outi[k] = (float)bi;
                row[bi] = -CUDART_INF_F;
            }
        }
        __syncthreads();
    }
}

extern "C" void kernel_launch(void* const* d_in, const int* in_sizes, int n_in,
                              void* d_out, int out_size)
{
    const float* x    = (const float*)d_in[0];
    const float* w    = (const float*)d_in[1];
    const float* bias = (const float*)d_in[2];
    float* out = (float*)d_out;

    void* nflag_ptr = nullptr;
    cudaGetSymbolAddress(&nflag_ptr, g_nflag);
    cudaMemsetAsync(nflag_ptr, 0, sizeof(int));

    cudaFuncSetAttribute(gate_kernel, cudaFuncAttributeMaxDynamicSharedMemorySize, SMEM_BYTES);
    gate_kernel<<<TOKENS / BM, THREADS, SMEM_BYTES>>>(x, w, bias, out);
    fix_kernel<<<512, 256>>>(x, w, bias, out);
}

// round 13
// speedup vs baseline: 1.7265x; 1.7265x over previous
#include <cuda_runtime.h>
#include <cstdint>
#include <math_constants.h>

#define TOKENS   32768
#define DIM      2048
#define NE       64
#define TOPK     6

#define BM       128              // tokens per CTA
#define BKT      32               // K per chunk
#define NCHUNK   (DIM / BKT)      // 64
#define THREADS  256              // 8 warps: 4 across M (32 rows), 2 across N (32 cols)

#define KB2      40               // bf16 row stride (elements): 32 + 8 pad -> conflict-free frags
#define ROWB     (KB2 * 2)        // 80 bytes per row

#define OFF_AH   0
#define OFF_AM   (BM * ROWB)                       // 10240
#define OFF_WH   (2 * BM * ROWB)                   // 20480
#define OFF_WM   (2 * BM * ROWB + NE * ROWB)       // 25600
#define STAGE_B  (2 * BM * ROWB + 2 * NE * ROWB)   // 30720
#define BIAS_OFF (2 * STAGE_B)
#define SMEM_BYTES (BIAS_OFF + 256)

#define LSTR     66               // epilogue logits row stride (floats)
#define FLAG_GAP 4e-6f            // ~8x above 4-term bf16 score noise (~5e-7)

// ---- flat flagged-token list ----
__device__ int g_nflag;
__device__ int g_flags[TOKENS];

// pack two fp32 -> bf16x2, round-to-nearest
__device__ __forceinline__ uint32_t pack_bf16(float hi, float lo) {
    uint32_t d;
    asm("cvt.rn.bf16x2.f32 %0, %1, %2;" : "=r"(d) : "f"(hi), "f"(lo));
    return d;
}
__device__ __forceinline__ float bf_lo(uint32_t p) { return __uint_as_float(p << 16); }
__device__ __forceinline__ float bf_hi(uint32_t p) { return __uint_as_float(p & 0xFFFF0000u); }

struct Duo { uint2 h, m; };
// 2-way bf16 split of 4 consecutive values: v ~= h + m (residual ~2^-18 rel)
__device__ __forceinline__ Duo split4(float4 v) {
    Duo t;
    t.h.x = pack_bf16(v.y, v.x);
    t.h.y = pack_bf16(v.w, v.z);
    float r0 = v.x - bf_lo(t.h.x), r1 = v.y - bf_hi(t.h.x);
    float r2 = v.z - bf_lo(t.h.y), r3 = v.w - bf_hi(t.h.y);
    t.m.x = pack_bf16(r1, r0);
    t.m.y = pack_bf16(r3, r2);
    return t;
}

// m16n8k16 bf16 mma, f32 accumulate in-place
__device__ __forceinline__ void mma16(float* c, const uint32_t* a, uint32_t b0, uint32_t b1) {
    asm volatile(
        "mma.sync.aligned.m16n8k16.row.col.f32.bf16.bf16.f32 "
        "{%0,%1,%2,%3}, {%4,%5,%6,%7}, {%8,%9}, {%0,%1,%2,%3};"
        : "+f"(c[0]), "+f"(c[1]), "+f"(c[2]), "+f"(c[3])
        : "r"(a[0]), "r"(a[1]), "r"(a[2]), "r"(a[3]), "r"(b0), "r"(b1));
}

// ============================ PASS 1: bf16 4-term MMA GEMM + gate ============================
__global__ __launch_bounds__(THREADS, 2)
void gate_kernel(const float* __restrict__ x,
                 const float* __restrict__ w,
                 const float* __restrict__ bias,
                 float* __restrict__ out)
{
    extern __shared__ __align__(16) unsigned char smem[];
    float* sBias = reinterpret_cast<float*>(smem + BIAS_OFF);
    float* sLog  = reinterpret_cast<float*>(smem);   // epilogue overlay

    const int tid  = threadIdx.x;
    const int lane = tid & 31;
    const int wid  = tid >> 5;
    const int gid  = lane >> 2;
    const int tg   = lane & 3;
    const int m0   = (wid & 3) * 32;
    const int n0   = (wid >> 2) * 32;
    const int block_m = blockIdx.x * BM;

    if (tid < NE) sBias[tid] = bias[tid];

    const float* xg = x + (size_t)block_m * DIM;

    float acc[2][4][4];
    #pragma unroll
    for (int mt = 0; mt < 2; mt++)
        #pragma unroll
        for (int nt = 0; nt < 4; nt++)
            #pragma unroll
            for (int r = 0; r < 4; r++) acc[mt][nt][r] = 0.f;

    float4 xr[4], wr[2];
    int xtok[4], xcq[4], wexp[2], wcq[2];
    #pragma unroll
    for (int i = 0; i < 4; i++) {
        int li = i * THREADS + tid; xtok[i] = li >> 3; xcq[i] = li & 7;
    }
    #pragma unroll
    for (int i = 0; i < 2; i++) {
        int li = i * THREADS + tid; wexp[i] = li >> 3; wcq[i] = li & 7;
    }

    auto ldg_chunk = [&](int c) {
        int k0 = c * BKT;
        #pragma unroll
        for (int i = 0; i < 4; i++)
            xr[i] = *reinterpret_cast<const float4*>(xg + (size_t)xtok[i] * DIM + k0 + xcq[i] * 4);
        #pragma unroll
        for (int i = 0; i < 2; i++)
            wr[i] = *reinterpret_cast<const float4*>(w + (size_t)wexp[i] * DIM + k0 + wcq[i] * 4);
    };
    auto sts_chunk = [&](int s) {
        unsigned char* st = smem + s * STAGE_B;
        #pragma unroll
        for (int i = 0; i < 4; i++) {
            Duo t = split4(xr[i]);
            int off = xtok[i] * ROWB + xcq[i] * 8;
            *reinterpret_cast<uint2*>(st + OFF_AH + off) = t.h;
            *reinterpret_cast<uint2*>(st + OFF_AM + off) = t.m;
        }
        #pragma unroll
        for (int i = 0; i < 2; i++) {
            Duo t = split4(wr[i]);
            int off = wexp[i] * ROWB + wcq[i] * 8;
            *reinterpret_cast<uint2*>(st + OFF_WH + off) = t.h;
            *reinterpret_cast<uint2*>(st + OFF_WM + off) = t.m;
        }
    };

    ldg_chunk(0);
    sts_chunk(0);
    __syncthreads();
    ldg_chunk(1);

    for (int c = 0; c < NCHUNK; c++) {
        const int s = c & 1;
        if (c + 1 < NCHUNK) {
            sts_chunk(s ^ 1);
            if (c + 2 < NCHUNK) ldg_chunk(c + 2);
        }

        const unsigned char* st = smem + s * STAGE_B;
        const uint32_t* Ah = reinterpret_cast<const uint32_t*>(st + OFF_AH);
        const uint32_t* Am = reinterpret_cast<const uint32_t*>(st + OFF_AM);
        const uint32_t* Wh = reinterpret_cast<const uint32_t*>(st + OFF_WH);
        const uint32_t* Wm = reinterpret_cast<const uint32_t*>(st + OFF_WM);

        #pragma unroll
        for (int q = 0; q < BKT / 16; q++) {
            const int kw = q * 8 + tg;

            uint32_t ah[2][4], am[2][4];
            #pragma unroll
            for (int mt = 0; mt < 2; mt++) {
                int r0 = (m0 + mt * 16 + gid) * (ROWB / 4);
                int r1 = r0 + 8 * (ROWB / 4);
                ah[mt][0] = Ah[r0 + kw];     ah[mt][1] = Ah[r1 + kw];
                ah[mt][2] = Ah[r0 + kw + 4]; ah[mt][3] = Ah[r1 + kw + 4];
                am[mt][0] = Am[r0 + kw];     am[mt][1] = Am[r1 + kw];
                am[mt][2] = Am[r0 + kw + 4]; am[mt][3] = Am[r1 + kw + 4];
            }

            #pragma unroll
            for (int nt = 0; nt < 4; nt++) {
                int rn = (n0 + nt * 8 + gid) * (ROWB / 4);
                uint32_t bh0 = Wh[rn + kw], bh1 = Wh[rn + kw + 4];
                uint32_t bm0 = Wm[rn + kw], bm1 = Wm[rn + kw + 4];
                #pragma unroll
                for (int mt = 0; mt < 2; mt++) {
                    float* cc = acc[mt][nt];
                    mma16(cc, ah[mt], bh0, bh1);   // hi*hi
                    mma16(cc, ah[mt], bm0, bm1);   // hi*mid
                    mma16(cc, am[mt], bh0, bh1);   // mid*hi
                    mma16(cc, am[mt], bm0, bm1);   // mid*mid
                }
            }
        }
        __syncthreads();
    }

    // ---- dump logits ----
    #pragma unroll
    for (int mt = 0; mt < 2; mt++)
        #pragma unroll
        for (int nt = 0; nt < 4; nt++) {
            int row = m0 + mt * 16 + gid;
            int col = n0 + nt * 8 + tg * 2;
            *reinterpret_cast<float2*>(&sLog[row * LSTR + col]) =
                make_float2(acc[mt][nt][0], acc[mt][nt][1]);
            *reinterpret_cast<float2*>(&sLog[(row + 8) * LSTR + col]) =
                make_float2(acc[mt][nt][2], acc[mt][nt][3]);
        }
    __syncthreads();

    // ---- epilogue: softmax, top-6, ambiguity flag ----
    if (tid < BM) {
        float* row = sLog + tid * LSTR;

        float m = row[0];
        #pragma unroll
        for (int e = 1; e < NE; e++) m = fmaxf(m, row[e]);
        float ssum = 0.f;
        #pragma unroll
        for (int e = 0; e < NE; e++) { float ex = __expf(row[e] - m); row[e] = ex; ssum += ex; }
        float inv = 1.0f / ssum;
        #pragma unroll
        for (int e = 0; e < NE; e++) row[e] *= inv;

        const int t = block_m + tid;
        float* outw = out + (size_t)t * TOPK;
        float* outi = out + (size_t)TOKENS * TOPK + (size_t)t * TOPK;

        float prev = 0.f, minGap = CUDART_INF_F;
        #pragma unroll
        for (int k = 0; k < TOPK + 1; k++) {
            float best = -CUDART_INF_F; int bi = 0;
            #pragma unroll
            for (int e = 0; e < NE; e++) {
                float b = row[e] + sBias[e];
                if (b > best) { best = b; bi = e; }
            }
            if (k > 0) minGap = fminf(minGap, prev - best);
            prev = best;
            if (k < TOPK) {
                outw[k] = row[bi];
                outi[k] = (float)bi;
                row[bi] = -CUDART_INF_F;
            }
        }
        if (minGap < FLAG_GAP) {
            int idx = atomicAdd(&g_nflag, 1);
            g_flags[idx] = t;
        }
    }
}

// ============ PASS 2: fp32 recompute for flagged tokens ============
// 1 block/token, 8 warps; warp handles 8 experts; lanes span k (coalesced).
__global__ __launch_bounds__(256)
void fix_kernel(const float* __restrict__ x,
                const float* __restrict__ w,
                const float* __restrict__ bias,
                float* __restrict__ out)
{
    __shared__ float row[NE];

    const int n    = g_nflag;
    const int lane = threadIdx.x & 31;
    const int warp = threadIdx.x >> 5;     // 0..7

    for (int i = blockIdx.x; i < n; i += gridDim.x) {
        const int tok = g_flags[i];
        const float* xt = x + (size_t)tok * DIM;

        #pragma unroll
        for (int j = 0; j < 8; j++) {
            const int e = warp * 8 + j;
            const float* wt = w + (size_t)e * DIM;

            float a = 0.f;
            #pragma unroll
            for (int kk = 0; kk < DIM / 128; kk++) {     // 16 iterations
                int k = kk * 128 + lane * 4;
                float4 xv = *reinterpret_cast<const float4*>(xt + k);
                float4 wv = *reinterpret_cast<const float4*>(wt + k);
                a = fmaf(xv.x, wv.x, a); a = fmaf(xv.y, wv.y, a);
                a = fmaf(xv.z, wv.z, a); a = fmaf(xv.w, wv.w, a);
            }
            // butterfly reduce
            #pragma unroll
            for (int off = 16; off > 0; off >>= 1)
                a += __shfl_xor_sync(0xFFFFFFFFu, a, off);
            if (lane == 0) row[e] = a;
        }
        __syncthreads();

        if (threadIdx.x == 0) {
            float m = row[0];
            #pragma unroll
            for (int q = 1; q < NE; q++) m = fmaxf(m, row[q]);
            float ssum = 0.f;
            #pragma unroll
            for (int q = 0; q < NE; q++) { float ex = __expf(row[q] - m); row[q] = ex; ssum += ex; }
            float inv = 1.0f / ssum;
            #pragma unroll
            for (int q = 0; q < NE; q++) row[q] *= inv;

            float* outw = out + (size_t)tok * TOPK;
            float* outi = out + (size_t)TOKENS * TOPK + (size_t)tok * TOPK;
            #pragma unroll
            for (int k = 0; k < TOPK; k++) {
                float best = -CUDART_INF_F; int bi = 0;
                #pragma unroll
                for (int q = 0; q < NE; q++) {
                    float b = row[q] + __ldg(&bias[q]);
                    if (b > best) { best = b; bi = q; }
                }
                outw[k] = row[bi];
                outi[k] = (float)bi;
                row[bi] = -CUDART_INF_F;
            }
        }
        __syncthreads();
    }
}

extern "C" void kernel_launch(void* const* d_in, const int* in_sizes, int n_in,
                              void* d_out, int out_size)
{
    const float* x    = (const float*)d_in[0];
    const float* w    = (const float*)d_in[1];
    const float* bias = (const float*)d_in[2];
    float* out = (float*)d_out;

    void* nflag_ptr = nullptr;
    cudaGetSymbolAddress(&nflag_ptr, g_nflag);
    cudaMemsetAsync(nflag_ptr, 0, sizeof(int));

    cudaFuncSetAttribute(gate_kernel, cudaFuncAttributeMaxDynamicSharedMemorySize, SMEM_BYTES);
    gate_kernel<<<TOKENS / BM, THREADS, SMEM_BYTES>>>(x, w, bias, out);
    fix_kernel<<<256, 256>>>(x, w, bias, out);
}